// round 2
// baseline (speedup 1.0000x reference)
#include <cuda_runtime.h>

// Problem constants (static per reference)
#define NIMG 8
#define CINC 64
#define HH   112
#define WW   112
#define NP   (HH*WW)      // 12544 patches per image
#define COUTC 64
#define DD   576          // CIN*K*K, feature order d = cin*9 + kh*3 + kw (torch unfold order)
#define MEM  1025

// Scratch (device globals — no allocation allowed)
__device__ float d_S[NIMG*NP];              // per-pixel channel sums
__device__ int   d_bins[NIMG*NP];           // bin per patch
__device__ int   d_first[NIMG*MEM];         // first-occurring patch idx per bin (init NP)
__device__ float d_rep[NIMG*MEM*COUTC];     // representative outputs
__device__ float d_Wt[DD*COUTC];            // transposed weight: Wt[d*64 + c]

// K1: channel sums + init first table + weight transpose (fused init pass)
__global__ void k_prep(const float* __restrict__ fmap,
                       const float* __restrict__ weight) {
    int tid = blockIdx.x * blockDim.x + threadIdx.x;

    if (tid < NIMG*MEM) d_first[tid] = NP;

    if (tid < COUTC*DD) {
        int c = tid / DD, d = tid - c*DD;
        d_Wt[d*COUTC + c] = weight[tid];
    }

    // tid = n*NP + p : sum fmap over 64 channels at this pixel (coalesced along p)
    {
        int n = tid / NP, p = tid - n*NP;
        const float* base = fmap + (size_t)n * CINC * NP + p;
        float s = 0.f;
        #pragma unroll
        for (int c = 0; c < CINC; c++) s += base[c*NP];
        d_S[tid] = s;
    }
}

// K2: 3x3 box sum (zero-padded) -> quantized bin -> scatter-min first occurrence
__global__ void k_bin() {
    int tid = blockIdx.x * blockDim.x + threadIdx.x;
    int n = tid / NP, p = tid - n*NP;
    int h = p / WW, w = p - h*WW;
    const float* S = d_S + n*NP;

    float sum = 0.f;
    #pragma unroll
    for (int dy = -1; dy <= 1; dy++) {
        int y = h + dy;
        if (y < 0 || y >= HH) continue;
        #pragma unroll
        for (int dx = -1; dx <= 1; dx++) {
            int x = w + dx;
            if (x < 0 || x >= WW) continue;
            sum += S[y*WW + x];
        }
    }
    float mean = sum / (float)DD;          // patches.mean(axis=2) incl. padded zeros
    int s = (int)(mean * 100.0f);          // trunc toward zero == astype(int32)
    int b = s + 512;                       // - MIN_SUMMARY
    b = b < 0 ? 0 : (b > MEM-1 ? MEM-1 : b);
    d_bins[tid] = b;
    atomicMin(&d_first[n*MEM + b], p);     // first-occurring patch index per bin
}

// K3: one block per (bin, image); only populated bins do work (~35/image).
// 64 threads: stage the 576-elem representative patch in shared, each thread
// computes one output channel as dot(patch, Wt[:,c]) + bias[c].
__global__ void __launch_bounds__(64) k_rep(const float* __restrict__ fmap,
                                            const float* __restrict__ bias) {
    int b = blockIdx.x, n = blockIdx.y;
    int p = d_first[n*MEM + b];
    if (p >= NP) return;                   // unused bin

    __shared__ float sh[DD];
    int t = threadIdx.x;
    int h = p / WW, w = p - (p / WW) * WW;

    for (int d = t; d < DD; d += 64) {
        int cin = d / 9, r = d - cin*9;
        int kh = r / 3, kw = r - kh*3;
        int y = h + kh - 1, x = w + kw - 1;
        float v = 0.f;
        if (y >= 0 && y < HH && x >= 0 && x < WW)
            v = fmap[(((size_t)n*CINC + cin)*HH + y)*WW + x];
        sh[d] = v;
    }
    __syncthreads();

    float acc = bias[t];
    #pragma unroll 8
    for (int d = 0; d < DD; d++)
        acc = fmaf(sh[d], d_Wt[d*COUTC + t], acc);   // coalesced Wt across warp

    d_rep[((size_t)n*MEM + b)*COUTC + t] = acc;
}

// K4: out[(n*64+c)*NP + p] = rep[n][bins[n][p]][c]  (coalesced writes)
__global__ void k_out(float* __restrict__ out) {
    int tid = blockIdx.x * blockDim.x + threadIdx.x;
    int p  = tid % NP;
    int nc = tid / NP;
    int c  = nc % COUTC;
    int n  = nc / COUTC;
    int b  = d_bins[n*NP + p];
    out[tid] = d_rep[((size_t)n*MEM + b)*COUTC + c];
}

extern "C" void kernel_launch(void* const* d_in, const int* in_sizes, int n_in,
                              void* d_out, int out_size) {
    const float* fmap   = (const float*)d_in[0];
    const float* weight = (const float*)d_in[1];
    const float* bias   = (const float*)d_in[2];
    float* out = (float*)d_out;

    (void)in_sizes; (void)n_in; (void)out_size;

    // 100352 threads covers channel-sum work and (as subsets) first-init + transpose
    k_prep<<<(NIMG*NP)/256, 256>>>(fmap, weight);
    k_bin<<<(NIMG*NP)/256, 256>>>();
    dim3 repGrid(MEM, NIMG);
    k_rep<<<repGrid, 64>>>(fmap, bias);
    k_out<<<(NIMG*COUTC*NP)/256, 256>>>(out);
}

// round 3
// speedup vs baseline: 1.2341x; 1.2341x over previous
#include <cuda_runtime.h>

// Problem constants (static per reference)
#define NIMG 8
#define CINC 64
#define HH   112
#define WW   112
#define NP   (HH*WW)      // 12544 pixels/patches per image
#define NP4  (NP/4)       // 3136 float4 groups per image
#define COUTC 64
#define DD   576          // CIN*K*K
#define MEM  1025

// Scratch (device globals — no allocation allowed)
__device__ float d_S[NIMG*NP];               // per-pixel channel sums
__device__ int   d_bins[NIMG*NP];            // bin per patch
__device__ int   d_first[NIMG*MEM];          // first-occurring patch idx per bin
__device__ float d_rep_t[NIMG*COUTC*MEM];    // representative outputs, TRANSPOSED: [n][c][bin]
__device__ float d_Wt[DD*COUTC];             // transposed weight: Wt[d*64 + c]

// K1: channel sums (float4, 4 px/thread) + init first table + weight transpose
__global__ void k_prep(const float* __restrict__ fmap,
                       const float* __restrict__ weight) {
    int tid   = blockIdx.x * blockDim.x + threadIdx.x;   // [0, NIMG*NP4)
    int total = gridDim.x * blockDim.x;

    for (int i = tid; i < NIMG*MEM; i += total) d_first[i] = NP;

    for (int i = tid; i < COUTC*DD; i += total) {
        int c = i / DD, d = i - c*DD;
        d_Wt[d*COUTC + c] = weight[i];
    }

    int n = tid / NP4, q = tid - n*NP4;
    const float4* base = (const float4*)(fmap + (size_t)n * CINC * NP) + q;
    float4 s = make_float4(0.f, 0.f, 0.f, 0.f);
    #pragma unroll
    for (int c = 0; c < CINC; c++) {
        float4 v = base[c * NP4];
        s.x += v.x; s.y += v.y; s.z += v.z; s.w += v.w;
    }
    ((float4*)d_S)[tid] = s;
}

// K2: 3x3 box sum (zero-padded) -> quantized bin -> scatter-min first occurrence.
// 4 pixels per thread (same row, w0 multiple of 4). FP accumulation order is
// row-major, left-to-right — identical to the validated scalar version.
__global__ void k_bin() {
    int tid = blockIdx.x * blockDim.x + threadIdx.x;     // [0, NIMG*NP4)
    int n = tid / NP4, q = tid - n*NP4;
    int p0 = q * 4;
    int h = p0 / WW, w0 = p0 - h*WW;
    const float* S = d_S + n*NP;

    float a0 = 0.f, a1 = 0.f, a2 = 0.f, a3 = 0.f;
    #pragma unroll
    for (int dy = -1; dy <= 1; dy++) {
        int y = h + dy;
        if (y < 0 || y >= HH) continue;
        const float* Sy = S + y*WW;
        float  left  = (w0 > 0)        ? Sy[w0 - 1] : 0.f;
        float4 mid   = *(const float4*)(Sy + w0);
        float  right = (w0 + 4 < WW)   ? Sy[w0 + 4] : 0.f;
        a0 += left  + mid.x + mid.y;
        a1 += mid.x + mid.y + mid.z;
        a2 += mid.y + mid.z + mid.w;
        a3 += mid.z + mid.w + right;
    }

    int4 b4;
    {
        float m; int s, b;
        m = a0 / (float)DD; s = (int)(m * 100.0f); b = s + 512;
        b4.x = b < 0 ? 0 : (b > MEM-1 ? MEM-1 : b);
        m = a1 / (float)DD; s = (int)(m * 100.0f); b = s + 512;
        b4.y = b < 0 ? 0 : (b > MEM-1 ? MEM-1 : b);
        m = a2 / (float)DD; s = (int)(m * 100.0f); b = s + 512;
        b4.z = b < 0 ? 0 : (b > MEM-1 ? MEM-1 : b);
        m = a3 / (float)DD; s = (int)(m * 100.0f); b = s + 512;
        b4.w = b < 0 ? 0 : (b > MEM-1 ? MEM-1 : b);
    }
    ((int4*)d_bins)[tid] = b4;

    int base = n*MEM;
    atomicMin(&d_first[base + b4.x], p0 + 0);
    atomicMin(&d_first[base + b4.y], p0 + 1);
    atomicMin(&d_first[base + b4.z], p0 + 2);
    atomicMin(&d_first[base + b4.w], p0 + 3);
}

// K3: one block per (bin, image); only populated bins do work (~35/image).
// 64 threads: stage the 576-elem representative patch in shared, each thread
// computes one output channel; result stored TRANSPOSED into d_rep_t[n][c][bin].
__global__ void __launch_bounds__(64) k_rep(const float* __restrict__ fmap,
                                            const float* __restrict__ bias) {
    int b = blockIdx.x, n = blockIdx.y;
    int p = d_first[n*MEM + b];
    if (p >= NP) return;                   // unused bin

    __shared__ float sh[DD];
    int t = threadIdx.x;
    int h = p / WW, w = p - h*WW;

    for (int d = t; d < DD; d += 64) {
        int cin = d / 9, r = d - cin*9;
        int kh = r / 3, kw = r - kh*3;
        int y = h + kh - 1, x = w + kw - 1;
        float v = 0.f;
        if (y >= 0 && y < HH && x >= 0 && x < WW)
            v = fmap[(((size_t)n*CINC + cin)*HH + y)*WW + x];
        sh[d] = v;
    }
    __syncthreads();

    float acc = bias[t];
    #pragma unroll 8
    for (int d = 0; d < DD; d++)
        acc = fmaf(sh[d], d_Wt[d*COUTC + t], acc);

    d_rep_t[((size_t)n*COUTC + t)*MEM + b] = acc;
}

// K4: gather + write. Each thread: one float4 pixel group, 8 output channels.
// One int4 bins load serves 8 float4 stores; rep_t gathers hit a small
// L1-resident region per (n,c) row.
#define CG 8
__global__ void k_out(float* __restrict__ out) {
    int tid = blockIdx.x * blockDim.x + threadIdx.x;  // [0, NIMG*(COUTC/CG)*NP4)
    int q    = tid % NP4;
    int rest = tid / NP4;
    int cg   = rest % (COUTC/CG);
    int n    = rest / (COUTC/CG);
    int c0   = cg * CG;

    int4 b4 = ((const int4*)d_bins)[n*NP4 + q];

    #pragma unroll
    for (int j = 0; j < CG; j++) {
        const float* rt = d_rep_t + ((size_t)n*COUTC + (c0 + j))*MEM;
        float4 o;
        o.x = rt[b4.x];
        o.y = rt[b4.y];
        o.z = rt[b4.z];
        o.w = rt[b4.w];
        ((float4*)out)[((size_t)n*COUTC + (c0 + j))*NP4 + q] = o;
    }
}

extern "C" void kernel_launch(void* const* d_in, const int* in_sizes, int n_in,
                              void* d_out, int out_size) {
    const float* fmap   = (const float*)d_in[0];
    const float* weight = (const float*)d_in[1];
    const float* bias   = (const float*)d_in[2];
    float* out = (float*)d_out;

    (void)in_sizes; (void)n_in; (void)out_size;

    k_prep<<<(NIMG*NP4 + 127)/128, 128>>>(fmap, weight);   // 196 blocks
    k_bin <<<(NIMG*NP4 + 127)/128, 128>>>();               // 196 blocks
    dim3 repGrid(MEM, NIMG);
    k_rep<<<repGrid, 64>>>(fmap, bias);
    k_out<<<(NIMG*(COUTC/CG)*NP4 + 255)/256, 256>>>(out);  // 784 blocks
}